// round 9
// baseline (speedup 1.0000x reference)
#include <cuda_runtime.h>
#include <cuda_fp16.h>
#include <cuda_fp8.h>
#include <math.h>

#define Nn 8
#define Cc 256
#define Ll 512
#define Kk 100
#define ROWS (Nn * Ll)          // 4096
#define INV_TEMP 2.0f           // 1/0.5
#define EPS 1e-8f

// Scratch (no runtime allocation allowed)
__device__ unsigned char g_z8[ROWS * Cc];  // z transposed + normalized, e5m2 (1MB)
__device__ __half g_ch[ROWS * Cc];         // c transposed + normalized * INV_TEMP

// ---------------------------------------------------------------------------
// Fused pre-pass: norms + transpose + normalize + quantize.
// grid=256: [which(2)][n(8)][ltile32(16)], block=512 (tx=l lane, ty=c group,
// 16 loads/thread -> half the latency chain of R8). Write phase: 16 lanes per
// row, rotation (i+w)&15 makes slab reads conflict-free; e5m2 packed to one
// uint4 store per 16 bytes.
// ---------------------------------------------------------------------------
__global__ void prep_k(const float* __restrict__ z, const float* __restrict__ c,
                       float* __restrict__ out)
{
    __shared__ float slab[Cc][33];
    __shared__ float part[16][33];
    __shared__ float inv_sh[32];

    int bb    = blockIdx.x;
    int lt    = bb & 15;
    int n     = (bb >> 4) & 7;
    int which = bb >> 7;

    if (bb == 0 && threadIdx.x == 0) out[0] = 0.0f;

    int cols = which ? (Ll + 1) : Ll;
    const float* src = (which ? c : z) + (size_t)n * Cc * cols + (which ? 1 : 0)
                     + lt * 32;

    int tx = threadIdx.x & 31;          // l lane
    int ty = threadIdx.x >> 5;          // c group 0..15 (16 c's each)

    float acc = 0.f;
#pragma unroll
    for (int i = 0; i < 16; i++) {
        int cc = ty * 16 + i;
        float v = src[(size_t)cc * cols + tx];
        slab[cc][tx] = v;
        acc += v * v;
    }
    part[ty][tx] = acc;
    __syncthreads();

    if (threadIdx.x < 32) {
        float s = 0.f;
#pragma unroll
        for (int k = 0; k < 16; k++) s += part[k][tx];
        float iv = 1.0f / fmaxf(sqrtf(s), EPS);
        if (which) iv *= INV_TEMP;
        inv_sh[tx] = iv;
    }
    __syncthreads();

    // Write phase: l = tid>>4 (0..31), w = tid&15 covers c in [16w, 16w+16).
    int l = threadIdx.x >> 4;
    int w = threadIdx.x & 15;
    float iv = inv_sh[l];
    int row = n * Ll + lt * 32 + l;

    if (which == 0) {
        __align__(16) unsigned char hh[16];
#pragma unroll
        for (int i = 0; i < 16; i++) {
            int ci = (i + w) & 15;                    // conflict-free rotation
            float v = slab[16 * w + ci][l] * iv;
            hh[ci] = (unsigned char)__nv_cvt_float_to_fp8(v, __NV_SATFINITE, __NV_E5M2);
        }
        ((uint4*)(g_z8 + (size_t)row * Cc))[w] = *(const uint4*)hh;
    } else {
        __align__(16) __half hh[16];
#pragma unroll
        for (int i = 0; i < 16; i++) {
            int ci = (i + w) & 15;
            hh[ci] = __float2half_rn(slab[16 * w + ci][l] * iv);
        }
        uint4* dst = (uint4*)(g_ch + (size_t)row * Cc) + 2 * w;
        dst[0] = ((const uint4*)hh)[0];
        dst[1] = ((const uint4*)hh)[1];
    }
}

// ---------------------------------------------------------------------------
// Main: one block per row, 128 threads = 16 octets (8 lanes). Octet o owns
// dots d = o + 16*it, it=0..6 (d==100 is the positive; d>100 wasted-uniform).
// Per dot: 256 B e5m2 row = 2 uint4/lane; decode via PRMT byte-shift
// (e5m2<<8 IS fp16); 16 HFMA2/lane; 3-shuffle octet reduction. Indices
// preloaded once and broadcast by shfl. Unroll 2 -> 4 LDG.128 in flight.
// ---------------------------------------------------------------------------
__global__ void logits_k(const int* __restrict__ neg_inds, float* __restrict__ out)
{
    __shared__ uint4 c_sh[32];
    __shared__ float logit_sh[Kk + 1];

    int row = blockIdx.x;
    int tid = threadIdx.x;
    int oct = tid >> 3;                 // 0..15
    int ol  = tid & 7;
    int ow8 = ((tid >> 3) & 3) * 8;     // octet base lane within warp

    if (tid < 32)
        c_sh[tid] = ((const uint4*)(g_ch + (size_t)row * Cc))[tid];

    // lane ol holds the gather index for it = ol (0..6)
    int jreg = row;
    if (ol < 7) {
        int d = oct + 16 * ol;
        if (d < Kk)
            jreg = __ldg(&neg_inds[(size_t)row * Kk + d]);
    }
    __syncthreads();

    // c elems [16*ol, +16) and [128+16*ol, +16) as 16 half2
    uint4 cax = c_sh[2 * ol], cay = c_sh[2 * ol + 1];
    uint4 cbx = c_sh[16 + 2 * ol], cby = c_sh[17 + 2 * ol];
    __half2 cA0 = *(__half2*)&cax.x, cA1 = *(__half2*)&cax.y;
    __half2 cA2 = *(__half2*)&cax.z, cA3 = *(__half2*)&cax.w;
    __half2 cA4 = *(__half2*)&cay.x, cA5 = *(__half2*)&cay.y;
    __half2 cA6 = *(__half2*)&cay.z, cA7 = *(__half2*)&cay.w;
    __half2 cB0 = *(__half2*)&cbx.x, cB1 = *(__half2*)&cbx.y;
    __half2 cB2 = *(__half2*)&cbx.z, cB3 = *(__half2*)&cbx.w;
    __half2 cB4 = *(__half2*)&cby.x, cB5 = *(__half2*)&cby.y;
    __half2 cB6 = *(__half2*)&cby.z, cB7 = *(__half2*)&cby.w;

#define DEC2(u, clo, chi, acc) do {                                           \
        unsigned _lo, _hi;                                                    \
        asm("prmt.b32 %0, %1, %2, 0x1404;" : "=r"(_lo) : "r"(u), "r"(0));     \
        asm("prmt.b32 %0, %1, %2, 0x3424;" : "=r"(_hi) : "r"(u), "r"(0));     \
        acc = __hfma2(*(__half2*)&_lo, clo, acc);                             \
        acc = __hfma2(*(__half2*)&_hi, chi, acc);                             \
    } while (0)

#define DOT(pa, pb, sval) do {                                                \
        __half2 a0 = __float2half2_rn(0.f), a1 = __float2half2_rn(0.f);       \
        DEC2(pa.x, cA0, cA1, a0); DEC2(pa.y, cA2, cA3, a1);                   \
        DEC2(pa.z, cA4, cA5, a0); DEC2(pa.w, cA6, cA7, a1);                   \
        DEC2(pb.x, cB0, cB1, a0); DEC2(pb.y, cB2, cB3, a1);                   \
        DEC2(pb.z, cB4, cB5, a0); DEC2(pb.w, cB6, cB7, a1);                   \
        __half2 at = __hadd2(a0, a1);                                         \
        float2 f = __half22float2(at);                                        \
        sval = f.x + f.y;                                                     \
    } while (0)

#pragma unroll 1
    for (int p = 0; p < 4; p++) {
        int it0 = 2 * p, it1 = 2 * p + 1;
        int j0 = __shfl_sync(0xffffffffu, jreg, ow8 + it0);
        int j1 = __shfl_sync(0xffffffffu, jreg, ow8 + it1);

        const uint4* zr0 = (const uint4*)(g_z8 + (size_t)j0 * Cc);
        const uint4* zr1 = (const uint4*)(g_z8 + (size_t)j1 * Cc);
        uint4 pa0 = zr0[ol];
        uint4 pb0 = zr0[8 + ol];
        uint4 pa1 = zr1[ol];
        uint4 pb1 = zr1[8 + ol];

        float s0, s1;
        DOT(pa0, pb0, s0);
        DOT(pa1, pb1, s1);
#pragma unroll
        for (int off = 4; off; off >>= 1) {
            s0 += __shfl_xor_sync(0xffffffffu, s0, off);
            s1 += __shfl_xor_sync(0xffffffffu, s1, off);
        }
        if (ol == 0) {
            int d0 = oct + 16 * it0;
            int d1 = oct + 16 * it1;
            if (d0 <= Kk) logit_sh[(d0 == Kk) ? 0 : d0 + 1] = s0;
            if (d1 <= Kk) logit_sh[(d1 == Kk) ? 0 : d1 + 1] = s1;
        }
    }
#undef DOT
#undef DEC2
    __syncthreads();

    if (tid < 32) {
        int lane = tid;
        float v0 = logit_sh[lane];
        float v1 = (lane + 32 < Kk + 1) ? logit_sh[lane + 32] : -INFINITY;
        float v2 = (lane + 64 < Kk + 1) ? logit_sh[lane + 64] : -INFINITY;
        float v3 = (lane + 96 < Kk + 1) ? logit_sh[lane + 96] : -INFINITY;
        float m = fmaxf(fmaxf(v0, v1), fmaxf(v2, v3));
#pragma unroll
        for (int off = 16; off; off >>= 1)
            m = fmaxf(m, __shfl_xor_sync(0xffffffffu, m, off));
        float e = __expf(v0 - m)
                + ((lane + 32 < Kk + 1) ? __expf(v1 - m) : 0.0f)
                + ((lane + 64 < Kk + 1) ? __expf(v2 - m) : 0.0f)
                + ((lane + 96 < Kk + 1) ? __expf(v3 - m) : 0.0f);
#pragma unroll
        for (int off = 16; off; off >>= 1)
            e += __shfl_xor_sync(0xffffffffu, e, off);
        if (lane == 0) {
            float item = m + logf(e) - logit_sh[0];
            atomicAdd(out, item * (1.0f / (float)ROWS));
        }
    }
}

extern "C" void kernel_launch(void* const* d_in, const int* in_sizes, int n_in,
                              void* d_out, int out_size)
{
    const float* z  = (const float*)d_in[0];   // (8, 256, 512)
    const float* c  = (const float*)d_in[1];   // (8, 256, 513)
    const int* inds = (const int*)d_in[2];     // (8, 512, 100)
    float* out = (float*)d_out;

    prep_k<<<256, 512>>>(z, c, out);
    logits_k<<<ROWS, 128>>>(inds, out);
}

// round 10
// speedup vs baseline: 1.3031x; 1.3031x over previous
#include <cuda_runtime.h>
#include <cuda_fp16.h>
#include <cuda_fp8.h>
#include <math.h>

#define Nn 8
#define Cc 256
#define Ll 512
#define Kk 100
#define ROWS (Nn * Ll)          // 4096
#define INV_TEMP 2.0f           // 1/0.5
#define EPS 1e-8f

// Scratch (no runtime allocation allowed)
__device__ unsigned char g_z8[ROWS * Cc];  // z transposed + normalized, e5m2 (1MB)
__device__ __half g_ch[ROWS * Cc];         // c transposed + normalized * INV_TEMP

// ---------------------------------------------------------------------------
// Fused pre-pass (R8 version — measured ~5.2us): norms + transpose +
// normalize + quantize. grid=256: [which(2)][n(8)][ltile32(16)], block=256.
// ---------------------------------------------------------------------------
__global__ void prep_k(const float* __restrict__ z, const float* __restrict__ c,
                       float* __restrict__ out)
{
    __shared__ float slab[Cc][33];
    __shared__ float part[8][33];
    __shared__ float inv_sh[32];

    int bb    = blockIdx.x;
    int lt    = bb & 15;
    int n     = (bb >> 4) & 7;
    int which = bb >> 7;

    if (bb == 0 && threadIdx.x == 0) out[0] = 0.0f;

    int cols = which ? (Ll + 1) : Ll;
    const float* src = (which ? c : z) + (size_t)n * Cc * cols + (which ? 1 : 0)
                     + lt * 32;

    int tx = threadIdx.x & 31;          // l lane
    int ty = threadIdx.x >> 5;          // c group

    float acc = 0.f;
#pragma unroll 8
    for (int i = 0; i < 32; i++) {
        int cc = ty * 32 + i;
        float v = src[(size_t)cc * cols + tx];
        slab[cc][tx] = v;
        acc += v * v;
    }
    part[ty][tx] = acc;
    __syncthreads();

    if (threadIdx.x < 32) {
        float s = 0.f;
#pragma unroll
        for (int k = 0; k < 8; k++) s += part[k][tx];
        float iv = 1.0f / fmaxf(sqrtf(s), EPS);
        if (which) iv *= INV_TEMP;
        inv_sh[tx] = iv;
    }
    __syncthreads();

    // Write phase: ty covers 4 l's; lanes sweep c contiguously.
#pragma unroll
    for (int i = 0; i < 4; i++) {
        int l   = ty * 4 + i;
        float iv = inv_sh[l];
        int row = n * Ll + lt * 32 + l;
        if (which == 0) {
            unsigned char* dst = g_z8 + (size_t)row * Cc;
#pragma unroll
            for (int ch = 0; ch < 8; ch++) {
                int c0 = ch * 32 + tx;
                float v = slab[c0][l] * iv;
                dst[c0] = (unsigned char)__nv_cvt_float_to_fp8(v, __NV_SATFINITE, __NV_E5M2);
            }
        } else {
            __half* dst = g_ch + (size_t)row * Cc;
#pragma unroll
            for (int ch = 0; ch < 8; ch++) {
                int c0 = ch * 32 + tx;
                dst[c0] = __float2half_rn(slab[c0][l] * iv);
            }
        }
    }
}

// ---------------------------------------------------------------------------
// Main (R9 version — measured 17.7us): one block per row, 128 threads =
// 16 octets (8 lanes). Octet o owns dots d = o + 16*it, it=0..6 (d==100 is
// the positive). Per dot: 256 B e5m2 row = 2 uint4/lane; PRMT byte-shift
// decode (e5m2<<8 IS fp16); 16 HFMA2/lane; 3-shuffle octet reduction.
// ---------------------------------------------------------------------------
__global__ void logits_k(const int* __restrict__ neg_inds, float* __restrict__ out)
{
    __shared__ uint4 c_sh[32];
    __shared__ float logit_sh[Kk + 1];

    int row = blockIdx.x;
    int tid = threadIdx.x;
    int oct = tid >> 3;                 // 0..15
    int ol  = tid & 7;
    int ow8 = ((tid >> 3) & 3) * 8;     // octet base lane within warp

    if (tid < 32)
        c_sh[tid] = ((const uint4*)(g_ch + (size_t)row * Cc))[tid];

    // lane ol holds the gather index for it = ol (0..6)
    int jreg = row;
    if (ol < 7) {
        int d = oct + 16 * ol;
        if (d < Kk)
            jreg = __ldg(&neg_inds[(size_t)row * Kk + d]);
    }
    __syncthreads();

    // c elems [16*ol, +16) and [128+16*ol, +16) as 16 half2
    uint4 cax = c_sh[2 * ol], cay = c_sh[2 * ol + 1];
    uint4 cbx = c_sh[16 + 2 * ol], cby = c_sh[17 + 2 * ol];
    __half2 cA0 = *(__half2*)&cax.x, cA1 = *(__half2*)&cax.y;
    __half2 cA2 = *(__half2*)&cax.z, cA3 = *(__half2*)&cax.w;
    __half2 cA4 = *(__half2*)&cay.x, cA5 = *(__half2*)&cay.y;
    __half2 cA6 = *(__half2*)&cay.z, cA7 = *(__half2*)&cay.w;
    __half2 cB0 = *(__half2*)&cbx.x, cB1 = *(__half2*)&cbx.y;
    __half2 cB2 = *(__half2*)&cbx.z, cB3 = *(__half2*)&cbx.w;
    __half2 cB4 = *(__half2*)&cby.x, cB5 = *(__half2*)&cby.y;
    __half2 cB6 = *(__half2*)&cby.z, cB7 = *(__half2*)&cby.w;

#define DEC2(u, clo, chi, acc) do {                                           \
        unsigned _lo, _hi;                                                    \
        asm("prmt.b32 %0, %1, %2, 0x1404;" : "=r"(_lo) : "r"(u), "r"(0));     \
        asm("prmt.b32 %0, %1, %2, 0x3424;" : "=r"(_hi) : "r"(u), "r"(0));     \
        acc = __hfma2(*(__half2*)&_lo, clo, acc);                             \
        acc = __hfma2(*(__half2*)&_hi, chi, acc);                             \
    } while (0)

#define DOT(pa, pb, sval) do {                                                \
        __half2 a0 = __float2half2_rn(0.f), a1 = __float2half2_rn(0.f);       \
        DEC2(pa.x, cA0, cA1, a0); DEC2(pa.y, cA2, cA3, a1);                   \
        DEC2(pa.z, cA4, cA5, a0); DEC2(pa.w, cA6, cA7, a1);                   \
        DEC2(pb.x, cB0, cB1, a0); DEC2(pb.y, cB2, cB3, a1);                   \
        DEC2(pb.z, cB4, cB5, a0); DEC2(pb.w, cB6, cB7, a1);                   \
        __half2 at = __hadd2(a0, a1);                                         \
        float2 f = __half22float2(at);                                        \
        sval = f.x + f.y;                                                     \
    } while (0)

#pragma unroll 1
    for (int p = 0; p < 4; p++) {
        int it0 = 2 * p, it1 = 2 * p + 1;
        int j0 = __shfl_sync(0xffffffffu, jreg, ow8 + it0);
        int j1 = __shfl_sync(0xffffffffu, jreg, ow8 + it1);

        const uint4* zr0 = (const uint4*)(g_z8 + (size_t)j0 * Cc);
        const uint4* zr1 = (const uint4*)(g_z8 + (size_t)j1 * Cc);
        uint4 pa0 = zr0[ol];
        uint4 pb0 = zr0[8 + ol];
        uint4 pa1 = zr1[ol];
        uint4 pb1 = zr1[8 + ol];

        float s0, s1;
        DOT(pa0, pb0, s0);
        DOT(pa1, pb1, s1);
#pragma unroll
        for (int off = 4; off; off >>= 1) {
            s0 += __shfl_xor_sync(0xffffffffu, s0, off);
            s1 += __shfl_xor_sync(0xffffffffu, s1, off);
        }
        if (ol == 0) {
            int d0 = oct + 16 * it0;
            int d1 = oct + 16 * it1;
            if (d0 <= Kk) logit_sh[(d0 == Kk) ? 0 : d0 + 1] = s0;
            if (d1 <= Kk) logit_sh[(d1 == Kk) ? 0 : d1 + 1] = s1;
        }
    }
#undef DOT
#undef DEC2
    __syncthreads();

    if (tid < 32) {
        int lane = tid;
        float v0 = logit_sh[lane];
        float v1 = (lane + 32 < Kk + 1) ? logit_sh[lane + 32] : -INFINITY;
        float v2 = (lane + 64 < Kk + 1) ? logit_sh[lane + 64] : -INFINITY;
        float v3 = (lane + 96 < Kk + 1) ? logit_sh[lane + 96] : -INFINITY;
        float m = fmaxf(fmaxf(v0, v1), fmaxf(v2, v3));
#pragma unroll
        for (int off = 16; off; off >>= 1)
            m = fmaxf(m, __shfl_xor_sync(0xffffffffu, m, off));
        float e = __expf(v0 - m)
                + ((lane + 32 < Kk + 1) ? __expf(v1 - m) : 0.0f)
                + ((lane + 64 < Kk + 1) ? __expf(v2 - m) : 0.0f)
                + ((lane + 96 < Kk + 1) ? __expf(v3 - m) : 0.0f);
#pragma unroll
        for (int off = 16; off; off >>= 1)
            e += __shfl_xor_sync(0xffffffffu, e, off);
        if (lane == 0) {
            float item = m + logf(e) - logit_sh[0];
            atomicAdd(out, item * (1.0f / (float)ROWS));
        }
    }
}

extern "C" void kernel_launch(void* const* d_in, const int* in_sizes, int n_in,
                              void* d_out, int out_size)
{
    const float* z  = (const float*)d_in[0];   // (8, 256, 512)
    const float* c  = (const float*)d_in[1];   // (8, 256, 513)
    const int* inds = (const int*)d_in[2];     // (8, 512, 100)
    float* out = (float*)d_out;

    prep_k<<<256, 256>>>(z, c, out);
    logits_k<<<ROWS, 128>>>(inds, out);
}

// round 11
// speedup vs baseline: 1.3407x; 1.0288x over previous
#include <cuda_runtime.h>
#include <math.h>

#define Nn 8
#define Cc 256
#define Ll 512
#define Kk 100
#define ROWS (Nn * Ll)          // 4096
#define INV_TEMP 2.0f           // 1/0.5
#define EPS 1e-8f
#define QSCALE 250.0f           // int8 quant scale for normalized rows
#define DEQ (INV_TEMP / (QSCALE * QSCALE))

// Scratch (no runtime allocation allowed)
__device__ signed char g_z8[ROWS * Cc];  // z transposed + normalized, int8*250 (1MB)
__device__ signed char g_c8[ROWS * Cc];  // c transposed + normalized, int8*250 (1MB)

// ---------------------------------------------------------------------------
// Fused pre-pass (R8 structure — measured ~5.2us): norms + transpose +
// normalize + int8 quantize. grid=256: [which(2)][n(8)][ltile32(16)], b=256.
// ---------------------------------------------------------------------------
__global__ void prep_k(const float* __restrict__ z, const float* __restrict__ c,
                       float* __restrict__ out)
{
    __shared__ float slab[Cc][33];
    __shared__ float part[8][33];
    __shared__ float inv_sh[32];

    int bb    = blockIdx.x;
    int lt    = bb & 15;
    int n     = (bb >> 4) & 7;
    int which = bb >> 7;

    if (bb == 0 && threadIdx.x == 0) out[0] = 0.0f;

    int cols = which ? (Ll + 1) : Ll;
    const float* src = (which ? c : z) + (size_t)n * Cc * cols + (which ? 1 : 0)
                     + lt * 32;

    int tx = threadIdx.x & 31;          // l lane
    int ty = threadIdx.x >> 5;          // c group

    float acc = 0.f;
#pragma unroll 8
    for (int i = 0; i < 32; i++) {
        int cc = ty * 32 + i;
        float v = src[(size_t)cc * cols + tx];
        slab[cc][tx] = v;
        acc += v * v;
    }
    part[ty][tx] = acc;
    __syncthreads();

    if (threadIdx.x < 32) {
        float s = 0.f;
#pragma unroll
        for (int k = 0; k < 8; k++) s += part[k][tx];
        inv_sh[tx] = QSCALE / fmaxf(sqrtf(s), EPS);
    }
    __syncthreads();

    // Write phase: ty covers 4 l's; lanes sweep c contiguously.
    signed char* gout = which ? g_c8 : g_z8;
#pragma unroll
    for (int i = 0; i < 4; i++) {
        int l   = ty * 4 + i;
        float iv = inv_sh[l];
        int row = n * Ll + lt * 32 + l;
        signed char* dst = gout + (size_t)row * Cc;
#pragma unroll
        for (int ch = 0; ch < 8; ch++) {
            int c0 = ch * 32 + tx;
            int b = __float2int_rn(slab[c0][l] * iv);
            b = max(-127, min(127, b));
            dst[c0] = (signed char)b;
        }
    }
}

// ---------------------------------------------------------------------------
// Main: one block per row, 128 threads = 16 octets (8 lanes). Octet o owns
// dots d = o + 16*it, it=0..6 (d==100 is the positive). Per dot: 256 B int8
// row = 2 uint4/lane; 8 DP4A/lane (int accumulate); 3-shuffle int reduce;
// one final float scale. Indices preloaded once and broadcast by shfl.
// ---------------------------------------------------------------------------
__global__ void logits_k(const int* __restrict__ neg_inds, float* __restrict__ out)
{
    __shared__ uint4 c_sh[16];
    __shared__ float logit_sh[Kk + 1];

    int row = blockIdx.x;
    int tid = threadIdx.x;
    int oct = tid >> 3;                 // 0..15
    int ol  = tid & 7;
    int ow8 = ((tid >> 3) & 3) * 8;     // octet base lane within warp

    if (tid < 16)
        c_sh[tid] = ((const uint4*)(g_c8 + (size_t)row * Cc))[tid];

    // lane ol holds the gather index for it = ol (0..6)
    int jreg = row;
    if (ol < 7) {
        int d = oct + 16 * ol;
        if (d < Kk)
            jreg = __ldg(&neg_inds[(size_t)row * Kk + d]);
    }
    __syncthreads();

    // this lane's 32 c bytes [32*ol, 32*ol+32)
    uint4 ca = c_sh[2 * ol];
    uint4 cb = c_sh[2 * ol + 1];
    int c0 = (int)ca.x, c1 = (int)ca.y, c2 = (int)ca.z, c3 = (int)ca.w;
    int c4 = (int)cb.x, c5 = (int)cb.y, c6 = (int)cb.z, c7 = (int)cb.w;

#define DOT(pa, pb, sval) do {                                                \
        int _s = 0;                                                           \
        _s = __dp4a((int)pa.x, c0, _s);                                       \
        _s = __dp4a((int)pa.y, c1, _s);                                       \
        _s = __dp4a((int)pa.z, c2, _s);                                       \
        _s = __dp4a((int)pa.w, c3, _s);                                       \
        _s = __dp4a((int)pb.x, c4, _s);                                       \
        _s = __dp4a((int)pb.y, c5, _s);                                       \
        _s = __dp4a((int)pb.z, c6, _s);                                       \
        _s = __dp4a((int)pb.w, c7, _s);                                       \
        sval = _s;                                                            \
    } while (0)

#pragma unroll 1
    for (int p = 0; p < 4; p++) {
        int it0 = 2 * p, it1 = 2 * p + 1;
        int j0 = __shfl_sync(0xffffffffu, jreg, ow8 + it0);
        int j1 = __shfl_sync(0xffffffffu, jreg, ow8 + it1);

        const uint4* zr0 = (const uint4*)(g_z8 + (size_t)j0 * Cc);
        const uint4* zr1 = (const uint4*)(g_z8 + (size_t)j1 * Cc);
        uint4 pa0 = zr0[2 * ol];
        uint4 pb0 = zr0[2 * ol + 1];
        uint4 pa1 = zr1[2 * ol];
        uint4 pb1 = zr1[2 * ol + 1];

        int s0, s1;
        DOT(pa0, pb0, s0);
        DOT(pa1, pb1, s1);
#pragma unroll
        for (int off = 4; off; off >>= 1) {
            s0 += __shfl_xor_sync(0xffffffffu, s0, off);
            s1 += __shfl_xor_sync(0xffffffffu, s1, off);
        }
        if (ol == 0) {
            int d0 = oct + 16 * it0;
            int d1 = oct + 16 * it1;
            if (d0 <= Kk) logit_sh[(d0 == Kk) ? 0 : d0 + 1] = (float)s0 * DEQ;
            if (d1 <= Kk) logit_sh[(d1 == Kk) ? 0 : d1 + 1] = (float)s1 * DEQ;
        }
    }
#undef DOT
    __syncthreads();

    if (tid < 32) {
        int lane = tid;
        float v0 = logit_sh[lane];
        float v1 = (lane + 32 < Kk + 1) ? logit_sh[lane + 32] : -INFINITY;
        float v2 = (lane + 64 < Kk + 1) ? logit_sh[lane + 64] : -INFINITY;
        float v3 = (lane + 96 < Kk + 1) ? logit_sh[lane + 96] : -INFINITY;
        float m = fmaxf(fmaxf(v0, v1), fmaxf(v2, v3));
#pragma unroll
        for (int off = 16; off; off >>= 1)
            m = fmaxf(m, __shfl_xor_sync(0xffffffffu, m, off));
        float e = __expf(v0 - m)
                + ((lane + 32 < Kk + 1) ? __expf(v1 - m) : 0.0f)
                + ((lane + 64 < Kk + 1) ? __expf(v2 - m) : 0.0f)
                + ((lane + 96 < Kk + 1) ? __expf(v3 - m) : 0.0f);
#pragma unroll
        for (int off = 16; off; off >>= 1)
            e += __shfl_xor_sync(0xffffffffu, e, off);
        if (lane == 0) {
            float item = m + logf(e) - logit_sh[0];
            atomicAdd(out, item * (1.0f / (float)ROWS));
        }
    }
}

extern "C" void kernel_launch(void* const* d_in, const int* in_sizes, int n_in,
                              void* d_out, int out_size)
{
    const float* z  = (const float*)d_in[0];   // (8, 256, 512)
    const float* c  = (const float*)d_in[1];   // (8, 256, 513)
    const int* inds = (const int*)d_in[2];     // (8, 512, 100)
    float* out = (float*)d_out;

    prep_k<<<256, 256>>>(z, c, out);
    logits_k<<<ROWS, 128>>>(inds, out);
}

// round 12
// speedup vs baseline: 1.4901x; 1.1115x over previous
#include <cuda_runtime.h>
#include <math.h>

#define Nn 8
#define Cc 256
#define Ll 512
#define Kk 100
#define ROWS (Nn * Ll)          // 4096
#define INV_TEMP 2.0f           // 1/0.5
#define EPS 1e-8f
#define QSCALE 250.0f           // int8 quant scale for normalized rows
#define DEQ (INV_TEMP / (QSCALE * QSCALE))

// Scratch (no runtime allocation allowed)
__device__ signed char g_z8[ROWS * Cc];  // z transposed + normalized, int8*250 (1MB)
__device__ signed char g_c8[ROWS * Cc];  // c transposed + normalized, int8*250 (1MB)

// ---------------------------------------------------------------------------
// Fused pre-pass (R8 structure — measured ~5.2us): norms + transpose +
// normalize + int8 quantize. grid=256: [which(2)][n(8)][ltile32(16)], b=256.
// ---------------------------------------------------------------------------
__global__ void prep_k(const float* __restrict__ z, const float* __restrict__ c,
                       float* __restrict__ out)
{
    __shared__ float slab[Cc][33];
    __shared__ float part[8][33];
    __shared__ float inv_sh[32];

    int bb    = blockIdx.x;
    int lt    = bb & 15;
    int n     = (bb >> 4) & 7;
    int which = bb >> 7;

    if (bb == 0 && threadIdx.x == 0) out[0] = 0.0f;

    int cols = which ? (Ll + 1) : Ll;
    const float* src = (which ? c : z) + (size_t)n * Cc * cols + (which ? 1 : 0)
                     + lt * 32;

    int tx = threadIdx.x & 31;          // l lane
    int ty = threadIdx.x >> 5;          // c group

    float acc = 0.f;
#pragma unroll 8
    for (int i = 0; i < 32; i++) {
        int cc = ty * 32 + i;
        float v = src[(size_t)cc * cols + tx];
        slab[cc][tx] = v;
        acc += v * v;
    }
    part[ty][tx] = acc;
    __syncthreads();

    if (threadIdx.x < 32) {
        float s = 0.f;
#pragma unroll
        for (int k = 0; k < 8; k++) s += part[k][tx];
        inv_sh[tx] = QSCALE / fmaxf(sqrtf(s), EPS);
    }
    __syncthreads();

    // Write phase: ty covers 4 l's; lanes sweep c contiguously.
    signed char* gout = which ? g_c8 : g_z8;
#pragma unroll
    for (int i = 0; i < 4; i++) {
        int l   = ty * 4 + i;
        float iv = inv_sh[l];
        int row = n * Ll + lt * 32 + l;
        signed char* dst = gout + (size_t)row * Cc;
#pragma unroll
        for (int ch = 0; ch < 8; ch++) {
            int c0 = ch * 32 + tx;
            int b = __float2int_rn(slab[c0][l] * iv);
            b = max(-127, min(127, b));
            dst[c0] = (signed char)b;
        }
    }
}

// ---------------------------------------------------------------------------
// Main: one block per row, 128 threads = 16 octets (8 lanes). Octet o owns
// dots d = o + 16*it, it=0..6 (d==100 is the positive). Per dot: 256 B int8
// row read CONTIGUOUSLY per instruction (lane ol takes bytes [16ol,+16) and
// [128+16ol,+16) -> one 128B line per octet per LDG). 8 DP4A/lane, 3-shuffle
// int reduce, one final float scale. Indices preloaded and shfl-broadcast.
// ---------------------------------------------------------------------------
__global__ void logits_k(const int* __restrict__ neg_inds, float* __restrict__ out)
{
    __shared__ uint4 c_sh[16];
    __shared__ float logit_sh[Kk + 1];

    int row = blockIdx.x;
    int tid = threadIdx.x;
    int oct = tid >> 3;                 // 0..15
    int ol  = tid & 7;
    int ow8 = ((tid >> 3) & 3) * 8;     // octet base lane within warp

    if (tid < 16)
        c_sh[tid] = ((const uint4*)(g_c8 + (size_t)row * Cc))[tid];

    // lane ol holds the gather index for it = ol (0..6)
    int jreg = row;
    if (ol < 7) {
        int d = oct + 16 * ol;
        if (d < Kk)
            jreg = __ldg(&neg_inds[(size_t)row * Kk + d]);
    }
    __syncthreads();

    // c bytes [16*ol, +16) and [128+16*ol, +16) — matches z load mapping
    uint4 ca = c_sh[ol];
    uint4 cb = c_sh[8 + ol];
    int c0 = (int)ca.x, c1 = (int)ca.y, c2 = (int)ca.z, c3 = (int)ca.w;
    int c4 = (int)cb.x, c5 = (int)cb.y, c6 = (int)cb.z, c7 = (int)cb.w;

#define DOT(pa, pb, sval) do {                                                \
        int _s = 0;                                                           \
        _s = __dp4a((int)pa.x, c0, _s);                                       \
        _s = __dp4a((int)pa.y, c1, _s);                                       \
        _s = __dp4a((int)pa.z, c2, _s);                                       \
        _s = __dp4a((int)pa.w, c3, _s);                                       \
        _s = __dp4a((int)pb.x, c4, _s);                                       \
        _s = __dp4a((int)pb.y, c5, _s);                                       \
        _s = __dp4a((int)pb.z, c6, _s);                                       \
        _s = __dp4a((int)pb.w, c7, _s);                                       \
        sval = _s;                                                            \
    } while (0)

#pragma unroll 1
    for (int p = 0; p < 4; p++) {
        int it0 = 2 * p, it1 = 2 * p + 1;
        int j0 = __shfl_sync(0xffffffffu, jreg, ow8 + it0);
        int j1 = __shfl_sync(0xffffffffu, jreg, ow8 + it1);

        const uint4* zr0 = (const uint4*)(g_z8 + (size_t)j0 * Cc);
        const uint4* zr1 = (const uint4*)(g_z8 + (size_t)j1 * Cc);
        uint4 pa0 = zr0[ol];        // contiguous 128B per octet
        uint4 pb0 = zr0[8 + ol];    // second 128B line
        uint4 pa1 = zr1[ol];
        uint4 pb1 = zr1[8 + ol];

        int s0, s1;
        DOT(pa0, pb0, s0);
        DOT(pa1, pb1, s1);
#pragma unroll
        for (int off = 4; off; off >>= 1) {
            s0 += __shfl_xor_sync(0xffffffffu, s0, off);
            s1 += __shfl_xor_sync(0xffffffffu, s1, off);
        }
        if (ol == 0) {
            int d0 = oct + 16 * it0;
            int d1 = oct + 16 * it1;
            if (d0 <= Kk) logit_sh[(d0 == Kk) ? 0 : d0 + 1] = (float)s0 * DEQ;
            if (d1 <= Kk) logit_sh[(d1 == Kk) ? 0 : d1 + 1] = (float)s1 * DEQ;
        }
    }
#undef DOT
    __syncthreads();

    if (tid < 32) {
        int lane = tid;
        float v0 = logit_sh[lane];
        float v1 = (lane + 32 < Kk + 1) ? logit_sh[lane + 32] : -INFINITY;
        float v2 = (lane + 64 < Kk + 1) ? logit_sh[lane + 64] : -INFINITY;
        float v3 = (lane + 96 < Kk + 1) ? logit_sh[lane + 96] : -INFINITY;
        float m = fmaxf(fmaxf(v0, v1), fmaxf(v2, v3));
#pragma unroll
        for (int off = 16; off; off >>= 1)
            m = fmaxf(m, __shfl_xor_sync(0xffffffffu, m, off));
        float e = __expf(v0 - m)
                + ((lane + 32 < Kk + 1) ? __expf(v1 - m) : 0.0f)
                + ((lane + 64 < Kk + 1) ? __expf(v2 - m) : 0.0f)
                + ((lane + 96 < Kk + 1) ? __expf(v3 - m) : 0.0f);
#pragma unroll
        for (int off = 16; off; off >>= 1)
            e += __shfl_xor_sync(0xffffffffu, e, off);
        if (lane == 0) {
            float item = m + logf(e) - logit_sh[0];
            atomicAdd(out, item * (1.0f / (float)ROWS));
        }
    }
}

extern "C" void kernel_launch(void* const* d_in, const int* in_sizes, int n_in,
                              void* d_out, int out_size)
{
    const float* z  = (const float*)d_in[0];   // (8, 256, 512)
    const float* c  = (const float*)d_in[1];   // (8, 256, 513)
    const int* inds = (const int*)d_in[2];     // (8, 512, 100)
    float* out = (float*)d_out;

    prep_k<<<256, 256>>>(z, c, out);
    logits_k<<<ROWS, 128>>>(inds, out);
}